// round 16
// baseline (speedup 1.0000x reference)
#include <cuda_runtime.h>
#include <cuda_fp16.h>
#include <cstdint>

#define DD 4096
#define BB 8192
#define OO 4096

// ---------------- scratch (device globals; no runtime alloc allowed) -------
static __device__ __half g_z[(size_t)BB * DD];   // 64 MB
static __device__ __half g_w[(size_t)OO * DD];   // 32 MB, holds W*U1
static __device__ float  g_c[BB];

// ---------------- helpers ---------------------------------------------------
__device__ __forceinline__ uint32_t smem_u32(const void* p) {
    uint32_t a;
    asm("{ .reg .u64 t; cvta.to.shared.u64 t, %1; cvt.u32.u64 %0, t; }" : "=r"(a) : "l"(p));
    return a;
}

__device__ __forceinline__ void cp_async16(uint32_t dst, const void* src) {
    asm volatile("cp.async.cg.shared.global [%0], [%1], 16;" :: "r"(dst), "l"(src));
}
__device__ __forceinline__ void cp_commit() {
    asm volatile("cp.async.commit_group;" ::: "memory");
}
template <int N>
__device__ __forceinline__ void cp_wait() {
    asm volatile("cp.async.wait_group %0;" :: "n"(N) : "memory");
}

__device__ __forceinline__ void ldsm_x4(uint32_t a[4], uint32_t addr) {
    asm volatile("ldmatrix.sync.aligned.m8n8.x4.shared.b16 {%0,%1,%2,%3}, [%4];"
                 : "=r"(a[0]), "=r"(a[1]), "=r"(a[2]), "=r"(a[3]) : "r"(addr));
}

// fp16-accumulate MMA, D/C chained in-place
__device__ __forceinline__ void mma16816_f16(uint32_t& d0, uint32_t& d1,
                                             const uint32_t a[4], const uint32_t b[2]) {
    asm volatile(
        "mma.sync.aligned.m16n8k16.row.col.f16.f16.f16.f16 "
        "{%0,%1}, {%2,%3,%4,%5}, {%6,%7}, {%0,%1};"
        : "+r"(d0), "+r"(d1)
        : "r"(a[0]), "r"(a[1]), "r"(a[2]), "r"(a[3]), "r"(b[0]), "r"(b[1]));
}

// zero-C form: d = a*b + 0
__device__ __forceinline__ void mma16816_f16_z(uint32_t& d0, uint32_t& d1,
                                               const uint32_t a[4], const uint32_t b[2]) {
    asm volatile(
        "mma.sync.aligned.m16n8k16.row.col.f16.f16.f16.f16 "
        "{%0,%1}, {%2,%3,%4,%5}, {%6,%7}, {%8,%9};"
        : "=r"(d0), "=r"(d1)
        : "r"(a[0]), "r"(a[1]), "r"(a[2]), "r"(a[3]), "r"(b[0]), "r"(b[1]),
          "r"(0u), "r"(0u));
}

__device__ __forceinline__ uint32_t pack_h2(float x, float y) {
    __half2 h = __floats2half2_rn(x, y);
    return *(uint32_t*)&h;
}

// ---------------- fused prep kernel -----------------------------------------
__global__ void __launch_bounds__(256) prep_kernel(const float* __restrict__ z,
                                                   const float* __restrict__ U1,
                                                   const float* __restrict__ U2,
                                                   const float* __restrict__ U3,
                                                   const float* __restrict__ W) {
    int t = threadIdx.x;
    if (blockIdx.x < BB) {
        int b = blockIdx.x;
        const float4* zr  = (const float4*)z + (size_t)b * (DD / 4);
        const float4* u2p = (const float4*)U2;
        const float4* u3p = (const float4*)U3;
        uint4* zo = (uint4*)(g_z + (size_t)b * DD);

        float s2 = 0.f, s3 = 0.f;
#pragma unroll
        for (int j = 0; j < 2; j++) {
            int i = j * 256 + t;
            float4 za = zr[2 * i];
            float4 zb = zr[2 * i + 1];
            float4 a2 = u2p[2 * i];
            float4 b2 = u2p[2 * i + 1];
            float4 a3 = u3p[2 * i];
            float4 b3 = u3p[2 * i + 1];
            s2 += za.x * a2.x + za.y * a2.y + za.z * a2.z + za.w * a2.w;
            s2 += zb.x * b2.x + zb.y * b2.y + zb.z * b2.z + zb.w * b2.w;
            s3 += za.x * a3.x + za.y * a3.y + za.z * a3.z + za.w * a3.w;
            s3 += zb.x * b3.x + zb.y * b3.y + zb.z * b3.z + zb.w * b3.w;
            uint4 pv;
            pv.x = pack_h2(za.x, za.y);
            pv.y = pack_h2(za.z, za.w);
            pv.z = pack_h2(zb.x, zb.y);
            pv.w = pack_h2(zb.z, zb.w);
            zo[i] = pv;
        }
#pragma unroll
        for (int o = 16; o > 0; o >>= 1) {
            s2 += __shfl_xor_sync(0xFFFFFFFFu, s2, o);
            s3 += __shfl_xor_sync(0xFFFFFFFFu, s3, o);
        }
        __shared__ float r2[8], r3[8];
        int wid = t >> 5, lid = t & 31;
        if (lid == 0) { r2[wid] = s2; r3[wid] = s3; }
        __syncthreads();
        if (t == 0) {
            float a = 0.f, c = 0.f;
#pragma unroll
            for (int i = 0; i < 8; i++) { a += r2[i]; c += r3[i]; }
            g_c[b] = a * c;
        }
    } else {
        const float4* w4 = (const float4*)W;
        const float4* u4 = (const float4*)U1;
        uint4* wo = (uint4*)g_w;
        size_t total = (size_t)OO * (DD / 8);
        size_t stride = (size_t)2048 * 256;
        for (size_t f = (size_t)(blockIdx.x - BB) * 256 + t; f < total; f += stride) {
            float4 wa = w4[2 * f];
            float4 wb = w4[2 * f + 1];
            size_t ui = (2 * f) & (DD / 4 - 1);
            float4 ua = u4[ui];
            float4 ub = u4[ui + 1];
            uint4 pv;
            pv.x = pack_h2(wa.x * ua.x, wa.y * ua.y);
            pv.y = pack_h2(wa.z * ua.z, wa.w * ua.w);
            pv.z = pack_h2(wb.x * ub.x, wb.y * ub.y);
            pv.w = pack_h2(wb.z * ub.z, wb.w * ub.w);
            wo[f] = pv;
        }
    }
}

// ---------------- GEMM ------------------------------------------------------
// Hybrid tensor+FMA: K = 3584 on tensor (56 iters of K64, HMMA rt16 floor) +
// 512 on the FMA pipe (HFMA2 into the same dch f16 chains, k-major smem
// buffer, 8 chunks of K64 transposed in via LDG->STS every 7 iters).
// Warp antiphase: odd warps [FMA-init -> chained MMA phases], even warps
// [zero-C MMA phases -> FMA], so one warp always feeds the tensor pipe.
#define TM 128
#define TN 256
#define TENSOR_K 3584
#define KITERS (TENSOR_K / 64)          // 56
#define STAGES 3
#define PITCH 144u
#define STG_A (TM * PITCH)              // 18432
#define STG_B (TN * PITCH)              // 36864
#define STG_BYTES (STG_A + STG_B)       // 55296
#define ZF_OFF (STAGES * STG_BYTES)     // 165888
#define ZF_PITCH 260
#define WF_OFF (ZF_OFF + 64 * ZF_PITCH) // 182528
#define WF_PITCH 516
#define GEMM_SMEM (WF_OFF + 64 * WF_PITCH)  // 215552

__global__ void __launch_bounds__(256, 1) gemm_kernel(const float* __restrict__ bias,
                                                      float* __restrict__ out) {
    extern __shared__ char smem[];
    uint32_t sb = smem_u32(smem);
    int tid = threadIdx.x;
    int wid = tid >> 5, lane = tid & 31;
    int m0 = blockIdx.y * TM;
    int n0 = blockIdx.x * TN;
    int wm = wid & 1;        // 2 M warp-groups of 64
    int wn = wid >> 1;       // 4 N warp-groups of 64

    float acc[4][8][4];
#pragma unroll
    for (int i = 0; i < 4; i++)
#pragma unroll
        for (int j = 0; j < 8; j++)
#pragma unroll
            for (int q = 0; q < 4; q++) acc[i][j][q] = 0.f;

    uint32_t dch[4][8][2];

    const __half* zb = g_z + (size_t)m0 * DD;
    const __half* wb = g_w + (size_t)n0 * DD;

    auto load_stage = [&](int st) {
        int s = st - (st / STAGES) * STAGES;
        uint32_t base = sb + (uint32_t)s * STG_BYTES;
        int kb = st * 64;
#pragma unroll
        for (int j = 0; j < 4; j++) {
            int c = tid + (j << 8);
            int r = c >> 3, ch = c & 7;
            cp_async16(base + (uint32_t)r * PITCH + (uint32_t)(ch << 4),
                       zb + (size_t)r * DD + kb + (ch << 3));
        }
#pragma unroll
        for (int j = 0; j < 8; j++) {
            int c = tid + (j << 8);
            int r = c >> 3, ch = c & 7;
            cp_async16(base + STG_A + (uint32_t)r * PITCH + (uint32_t)(ch << 4),
                       wb + (size_t)r * DD + kb + (ch << 3));
        }
        cp_commit();
    };

#pragma unroll
    for (int p = 0; p < STAGES - 1; p++) load_stage(p);

    // intra-warp ldmatrix offsets
    uint32_t a_row = (uint32_t)(wm * 64 + (lane & 15));
    uint32_t a_kof = (uint32_t)((lane >> 4) << 3) * 2u;
    uint32_t b_row = (uint32_t)(wn * 64 + ((lane >> 4) << 3) + (lane & 7));
    uint32_t b_kof = (uint32_t)(((lane >> 3) & 1) << 3) * 2u;

    // FMA-slice smem base offsets (per-thread components)
    const char* zf_l = smem + ZF_OFF + (size_t)((wm * 64) + (lane >> 2)) * 2;
    const char* wf_l = smem + WF_OFF + (size_t)((wn * 64) + (lane & 3) * 2) * 2;

    auto promote = [&]() {
#pragma unroll
        for (int mi = 0; mi < 4; mi++)
#pragma unroll
            for (int nj = 0; nj < 8; nj++) {
                float2 f0 = __half22float2(*(__half2*)&dch[mi][nj][0]);
                float2 f1 = __half22float2(*(__half2*)&dch[mi][nj][1]);
                acc[mi][nj][0] += f0.x;
                acc[mi][nj][1] += f0.y;
                acc[mi][nj][2] += f1.x;
                acc[mi][nj][3] += f1.y;
            }
    };

    // one k-column of the FMA slice; 'first' initializes dch via mul
    auto fma_k = [&](int kk, bool first) {
        const char* za = zf_l + kk * ZF_PITCH;
        const char* wa = wf_l + kk * WF_PITCH;
        uint32_t wp[8];
#pragma unroll
        for (int nj = 0; nj < 8; nj++)
            wp[nj] = *(const uint32_t*)(wa + nj * 16);
#pragma unroll
        for (int mi = 0; mi < 4; mi++) {
            __half z0 = *(const __half*)(za + mi * 32);
            __half z1 = *(const __half*)(za + mi * 32 + 16);
            __half2 s0 = __half2half2(z0);
            __half2 s1 = __half2half2(z1);
#pragma unroll
            for (int nj = 0; nj < 8; nj++) {
                __half2 w2 = *(__half2*)&wp[nj];
                if (first) {
                    *(__half2*)&dch[mi][nj][0] = __hmul2(s0, w2);
                    *(__half2*)&dch[mi][nj][1] = __hmul2(s1, w2);
                } else {
                    *(__half2*)&dch[mi][nj][0] = __hfma2(s0, w2, *(__half2*)&dch[mi][nj][0]);
                    *(__half2*)&dch[mi][nj][1] = __hfma2(s1, w2, *(__half2*)&dch[mi][nj][1]);
                }
            }
        }
    };

    auto fma_blk = [&](int r7, bool init) {
        int p = r7 - 2;
        int ks0 = p * 13;
        int kcnt = (p == 4) ? 12 : 13;
        if (init) { fma_k(ks0, true); ks0++; kcnt--; }
        for (int kk = ks0; kk < ks0 + kcnt; ++kk) fma_k(kk, false);
    };

    auto phases = [&](uint32_t aS, uint32_t bS, bool zc, bool prom) {
        // phase 0
        uint32_t bf[4][4];
#pragma unroll
        for (int pj = 0; pj < 4; pj++)
            ldsm_x4(bf[pj], bS + (b_row + (uint32_t)(pj * 16)) * PITCH + b_kof);
        uint32_t af0[4];
        ldsm_x4(af0, aS + a_row * PITCH + a_kof);
        if (prom) promote();
#pragma unroll
        for (int mi = 0; mi < 4; mi++) {
            uint32_t af[4];
            if (mi == 0) {
#pragma unroll
                for (int q = 0; q < 4; q++) af[q] = af0[q];
            } else {
                ldsm_x4(af, aS + (a_row + (uint32_t)(mi * 16)) * PITCH + a_kof);
            }
#pragma unroll
            for (int nj = 0; nj < 8; nj++) {
                if (zc)
                    mma16816_f16_z(dch[mi][nj][0], dch[mi][nj][1],
                                   af, &bf[nj >> 1][(nj & 1) * 2]);
                else
                    mma16816_f16(dch[mi][nj][0], dch[mi][nj][1],
                                 af, &bf[nj >> 1][(nj & 1) * 2]);
            }
        }
        // phases 1..3: chained
#pragma unroll
        for (int ks = 1; ks < 4; ks++) {
            uint32_t koff = (uint32_t)(ks * 32);
#pragma unroll
            for (int pj = 0; pj < 4; pj++)
                ldsm_x4(bf[pj], bS + (b_row + (uint32_t)(pj * 16)) * PITCH + koff + b_kof);
#pragma unroll
            for (int mi = 0; mi < 4; mi++) {
                uint32_t af[4];
                ldsm_x4(af, aS + (a_row + (uint32_t)(mi * 16)) * PITCH + koff + a_kof);
#pragma unroll
                for (int nj = 0; nj < 8; nj++)
                    mma16816_f16(dch[mi][nj][0], dch[mi][nj][1],
                                 af, &bf[nj >> 1][(nj & 1) * 2]);
            }
        }
    };

    for (int it = 0; it < KITERS; ++it) {
        if (it < KITERS - 1) cp_wait<1>();
        else                 cp_wait<0>();
        __syncthreads();

        if (it + STAGES - 1 < KITERS) load_stage(it + STAGES - 1);

        int r7 = it % 7;

        // transpose-load FMA chunk (k-major) every 7 iters
        if (r7 == 0) {
            int j = it / 7;                       // 0..7
            int kf = TENSOR_K + 64 * j;
            if (tid < 128) {
                int m = tid;
                const uint4* src = (const uint4*)(g_z + (size_t)(m0 + m) * DD + kf);
#pragma unroll
                for (int k8 = 0; k8 < 8; k8++) {
                    uint4 v = src[k8];
                    uint32_t w4v[4] = {v.x, v.y, v.z, v.w};
#pragma unroll
                    for (int q = 0; q < 4; q++) {
                        uint32_t u = w4v[q];
                        int kloc = k8 * 8 + q * 2;
                        *(__half*)(smem + ZF_OFF + kloc * ZF_PITCH + m * 2) =
                            __ushort_as_half((unsigned short)(u & 0xFFFF));
                        *(__half*)(smem + ZF_OFF + (kloc + 1) * ZF_PITCH + m * 2) =
                            __ushort_as_half((unsigned short)(u >> 16));
                    }
                }
            } else {
                int mt = tid - 128;
#pragma unroll
                for (int rr = 0; rr < 2; rr++) {
                    int n = mt * 2 + rr;
                    const uint4* src = (const uint4*)(g_w + (size_t)(n0 + n) * DD + kf);
#pragma unroll
                    for (int k8 = 0; k8 < 8; k8++) {
                        uint4 v = src[k8];
                        uint32_t w4v[4] = {v.x, v.y, v.z, v.w};
#pragma unroll
                        for (int q = 0; q < 4; q++) {
                            uint32_t u = w4v[q];
                            int kloc = k8 * 8 + q * 2;
                            *(__half*)(smem + WF_OFF + kloc * WF_PITCH + n * 2) =
                                __ushort_as_half((unsigned short)(u & 0xFFFF));
                            *(__half*)(smem + WF_OFF + (kloc + 1) * WF_PITCH + n * 2) =
                                __ushort_as_half((unsigned short)(u >> 16));
                        }
                    }
                }
            }
        }

        int s = it - (it / STAGES) * STAGES;
        uint32_t aS = sb + (uint32_t)s * STG_BYTES;
        uint32_t bS = aS + STG_A;

        bool cons = (r7 >= 2);
        if ((wid & 1) && cons) {
            // odd warp: promote, FMA-init chain, then chained MMA phases
            if (it) promote();
            fma_blk(r7, true);
            phases(aS, bS, false, false);
        } else {
            // even warp (or non-consume): zero-C phases (promote in LDSM shadow)
            phases(aS, bS, true, it > 0);
            if (cons) fma_blk(r7, false);
        }
    }

    // final promote
    promote();
    __syncthreads();

    // epilogue: out = c[m]*acc + bias[n]
    int col_base = n0 + wn * 64 + (lane & 3) * 2;
    float bb[8][2];
#pragma unroll
    for (int nj = 0; nj < 8; nj++) {
        bb[nj][0] = __ldg(bias + col_base + nj * 8);
        bb[nj][1] = __ldg(bias + col_base + nj * 8 + 1);
    }
#pragma unroll
    for (int mi = 0; mi < 4; mi++) {
        int r0 = m0 + wm * 64 + mi * 16 + (lane >> 2);
        float c0 = __ldg(g_c + r0);
        float c1 = __ldg(g_c + r0 + 8);
        float* o0 = out + (size_t)r0 * OO;
        float* o1 = o0 + (size_t)8 * OO;
#pragma unroll
        for (int nj = 0; nj < 8; nj++) {
            int col = col_base + nj * 8;
            float2 v0, v1;
            v0.x = c0 * acc[mi][nj][0] + bb[nj][0];
            v0.y = c0 * acc[mi][nj][1] + bb[nj][1];
            v1.x = c1 * acc[mi][nj][2] + bb[nj][0];
            v1.y = c1 * acc[mi][nj][3] + bb[nj][1];
            *(float2*)(o0 + col) = v0;
            *(float2*)(o1 + col) = v1;
        }
    }
}

// ---------------- launch ----------------------------------------------------
extern "C" void kernel_launch(void* const* d_in, const int* in_sizes, int n_in,
                              void* d_out, int out_size) {
    (void)in_sizes; (void)n_in; (void)out_size;
    const float* z    = (const float*)d_in[0];
    const float* U1   = (const float*)d_in[1];
    const float* U2   = (const float*)d_in[2];
    const float* U3   = (const float*)d_in[3];
    const float* W    = (const float*)d_in[4];
    const float* bias = (const float*)d_in[5];
    float* out = (float*)d_out;

    prep_kernel<<<BB + 2048, 256>>>(z, U1, U2, U3, W);

    static bool attr_set = false;
    if (!attr_set) {
        cudaFuncSetAttribute(gemm_kernel, cudaFuncAttributeMaxDynamicSharedMemorySize,
                             GEMM_SMEM);
        attr_set = true;
    }
    dim3 grid(OO / TN, BB / TM);
    gemm_kernel<<<grid, 256, GEMM_SMEM>>>(bias, out);
}